// round 1
// baseline (speedup 1.0000x reference)
#include <cuda_runtime.h>
#include <cuda_bf16.h>
#include <math.h>

// Problem constants
#define BATCH   8
#define SEQ     4096
#define DIM     1024
#define ROWS    (BATCH * SEQ)         // 32768
#define HEADS   4
#define DHEAD   32
#define HID     (HEADS * DHEAD)       // 128
#define QKVN    (3 * HID)             // 384
#define NCHUNK  32                    // sequence chunks for ctx partials (4096/128)
#define EPS     1e-5f
#define SCALE   0.17677669529663688f  // 32^-0.5

// ---------------------------------------------------------------------------
// Scratch (static device globals; allocation-free per harness rules)
// ---------------------------------------------------------------------------
__device__ __nv_bfloat16 g_xn[(size_t)ROWS * DIM];          // 64 MB
__device__ float         g_qkv[(size_t)ROWS * QKVN];        // 48 MB
__device__ float         g_pctx[NCHUNK * BATCH * HEADS * DHEAD * DHEAD]; // 4 MB
__device__ float         g_pS[NCHUNK * BATCH * HID];        // 128 KB
__device__ float         g_ctx[BATCH * HEADS * DHEAD * DHEAD]; // 128 KB

// ---------------------------------------------------------------------------
// K1: LayerNorm over channel dim, output bf16
// grid = ROWS blocks, 256 threads; each thread handles one float4 of the row
// ---------------------------------------------------------------------------
__global__ __launch_bounds__(256) void k_ln(const float* __restrict__ x,
                                            const float* __restrict__ gamma,
                                            const float* __restrict__ beta) {
    const int row = blockIdx.x;
    const int tid = threadIdx.x;
    const float4* xr = (const float4*)(x + (size_t)row * DIM);
    float4 f = xr[tid];

    float s  = f.x + f.y + f.z + f.w;
    float s2 = fmaf(f.x, f.x, fmaf(f.y, f.y, fmaf(f.z, f.z, f.w * f.w)));

    // warp reduce
    #pragma unroll
    for (int off = 16; off > 0; off >>= 1) {
        s  += __shfl_xor_sync(0xffffffffu, s,  off);
        s2 += __shfl_xor_sync(0xffffffffu, s2, off);
    }
    __shared__ float red[16];
    const int wid = tid >> 5, lane = tid & 31;
    if (lane == 0) { red[wid] = s; red[8 + wid] = s2; }
    __syncthreads();
    float ts = 0.f, ts2 = 0.f;
    #pragma unroll
    for (int w = 0; w < 8; ++w) { ts += red[w]; ts2 += red[8 + w]; }

    const float mean = ts * (1.0f / DIM);
    const float var  = ts2 * (1.0f / DIM) - mean * mean;
    const float rstd = rsqrtf(var + EPS);

    const float4 g  = ((const float4*)gamma)[tid];
    const float4 be = ((const float4*)beta)[tid];
    float a0 = (f.x - mean) * rstd * g.x + be.x;
    float a1 = (f.y - mean) * rstd * g.y + be.y;
    float a2 = (f.z - mean) * rstd * g.z + be.z;
    float a3 = (f.w - mean) * rstd * g.w + be.w;

    __nv_bfloat162* o = (__nv_bfloat162*)(g_xn + (size_t)row * DIM);
    __nv_bfloat162 p0; p0.x = __float2bfloat16(a0); p0.y = __float2bfloat16(a1);
    __nv_bfloat162 p1; p1.x = __float2bfloat16(a2); p1.y = __float2bfloat16(a3);
    o[tid * 2 + 0] = p0;
    o[tid * 2 + 1] = p1;
}

// ---------------------------------------------------------------------------
// K2: QKV GEMM  C[32768,384] = xn_bf16[32768,1024] @ w_qkv[1024,384]
// BM=128, BN=128, BK=16, 256 threads, 8x8 per thread, fp32 accumulate
// grid = (3, 256)
// ---------------------------------------------------------------------------
__global__ __launch_bounds__(256) void k_gemm_qkv(const float* __restrict__ B) {
    __shared__ float As[16][132];
    __shared__ float Bs[16][132];

    const int tid  = threadIdx.x;
    const int bcol = blockIdx.x;     // 0..2
    const int brow = blockIdx.y;     // 0..255
    const int tx = tid & 15;         // 0..15 (cols)
    const int ty = tid >> 4;         // 0..15 (rows)

    const int au  = tid & 7;         // bf16x2 column within 16-wide K tile
    const int ar0 = tid >> 3;        // 0..31 row base
    const int bc4 = tid & 31;        // float4 col
    const int bk0 = tid >> 5;        // 0..7 k-row base

    float acc[8][8];
    #pragma unroll
    for (int i = 0; i < 8; ++i)
        #pragma unroll
        for (int j = 0; j < 8; ++j) acc[i][j] = 0.f;

    for (int kt = 0; kt < DIM; kt += 16) {
        // Load A tile (128 x 16 bf16) -> fp32 transposed into As[k][m]
        #pragma unroll
        for (int p = 0; p < 4; ++p) {
            const int r = ar0 + p * 32;
            const __nv_bfloat162 v =
                *(const __nv_bfloat162*)(g_xn + (size_t)(brow * 128 + r) * DIM + kt + au * 2);
            As[au * 2 + 0][r] = __bfloat162float(v.x);
            As[au * 2 + 1][r] = __bfloat162float(v.y);
        }
        // Load B tile (16 x 128 fp32)
        #pragma unroll
        for (int p = 0; p < 2; ++p) {
            const int kr = bk0 + p * 8;
            const float4 v =
                *(const float4*)(B + (size_t)(kt + kr) * QKVN + bcol * 128 + bc4 * 4);
            *(float4*)&Bs[kr][bc4 * 4] = v;
        }
        __syncthreads();

        #pragma unroll
        for (int kk = 0; kk < 16; ++kk) {
            float4 a0 = *(const float4*)&As[kk][ty * 8];
            float4 a1 = *(const float4*)&As[kk][ty * 8 + 4];
            float4 b0 = *(const float4*)&Bs[kk][tx * 8];
            float4 b1 = *(const float4*)&Bs[kk][tx * 8 + 4];
            float a[8] = {a0.x, a0.y, a0.z, a0.w, a1.x, a1.y, a1.z, a1.w};
            float bb[8] = {b0.x, b0.y, b0.z, b0.w, b1.x, b1.y, b1.z, b1.w};
            #pragma unroll
            for (int i = 0; i < 8; ++i)
                #pragma unroll
                for (int j = 0; j < 8; ++j)
                    acc[i][j] = fmaf(a[i], bb[j], acc[i][j]);
        }
        __syncthreads();
    }

    // Store C
    #pragma unroll
    for (int i = 0; i < 8; ++i) {
        const size_t r = (size_t)(brow * 128 + ty * 8 + i);
        #pragma unroll
        for (int j4 = 0; j4 < 2; ++j4) {
            float4 v = {acc[i][j4 * 4 + 0], acc[i][j4 * 4 + 1],
                        acc[i][j4 * 4 + 2], acc[i][j4 * 4 + 3]};
            *(float4*)(g_qkv + r * QKVN + bcol * 128 + tx * 8 + j4 * 4) = v;
        }
    }
}

// ---------------------------------------------------------------------------
// K3: per-chunk partials of exp(k)*v and column-sums of exp(k)
// grid = (NCHUNK, HEADS, BATCH), 256 threads
// ---------------------------------------------------------------------------
__global__ __launch_bounds__(256) void k_ctx_part() {
    const int chunk = blockIdx.x;
    const int h     = blockIdx.y;
    const int b     = blockIdx.z;
    const int tid   = threadIdx.x;

    __shared__ float ks[128][32];
    __shared__ float vs[128][32];

    const int f4 = tid & 7;      // float4 index within 32 cols
    const int r0 = tid >> 3;     // 0..31

    const size_t base = (size_t)(b * SEQ + chunk * 128) * QKVN;
    #pragma unroll
    for (int p = 0; p < 4; ++p) {
        const int r = r0 + p * 32;
        const size_t rb = base + (size_t)r * QKVN;
        float4 kv = *(const float4*)(g_qkv + rb + HID + h * DHEAD + f4 * 4);
        ks[r][f4 * 4 + 0] = expf(kv.x);
        ks[r][f4 * 4 + 1] = expf(kv.y);
        ks[r][f4 * 4 + 2] = expf(kv.z);
        ks[r][f4 * 4 + 3] = expf(kv.w);
        float4 vv = *(const float4*)(g_qkv + rb + 2 * HID + h * DHEAD + f4 * 4);
        *(float4*)&vs[r][f4 * 4] = vv;
    }
    __syncthreads();

    // partial S_d
    if (tid < 32) {
        float s = 0.f;
        #pragma unroll
        for (int r = 0; r < 128; ++r) s += ks[r][tid];
        g_pS[chunk * (BATCH * HID) + b * HID + h * DHEAD + tid] = s;
    }

    // partial context: each thread owns 4 (d,e) entries; d broadcast per warp
    const int e  = tid & 31;
    const int d0 = tid >> 5;      // 0..7
    float acc[4] = {0.f, 0.f, 0.f, 0.f};
    for (int r = 0; r < 128; ++r) {
        const float ve = vs[r][e];
        #pragma unroll
        for (int i = 0; i < 4; ++i)
            acc[i] = fmaf(ks[r][d0 + i * 8], ve, acc[i]);
    }
    const size_t ob = (size_t)chunk * 32768 + (size_t)b * 4096 + (size_t)h * 1024;
    #pragma unroll
    for (int i = 0; i < 4; ++i)
        g_pctx[ob + (size_t)(d0 + i * 8) * 32 + e] = acc[i];
}

// ---------------------------------------------------------------------------
// K4: reduce partials, fold softmax normalization and q-scale into ctx
// grid = 32 blocks x 1024 threads (32768 ctx entries)
// ---------------------------------------------------------------------------
__global__ __launch_bounds__(1024) void k_ctx_reduce() {
    const int o  = blockIdx.x * 1024 + threadIdx.x;  // b*4096 + h*1024 + d*32 + e
    const int bi = o >> 12;
    const int hd = (o >> 5) & 127;                   // h*32+d
    float s = 0.f, S = 0.f;
    #pragma unroll
    for (int c = 0; c < NCHUNK; ++c) {
        s += g_pctx[(size_t)c * 32768 + o];
        S += g_pS[c * (BATCH * HID) + bi * HID + hd];
    }
    g_ctx[o] = s * SCALE / S;
}

// ---------------------------------------------------------------------------
// K5: fused  oa = q @ ctx  ->  out = oa @ w_out + b_out + x
// grid = 1024 row-blocks (32 rows each), 256 threads
// ---------------------------------------------------------------------------
__global__ __launch_bounds__(256) void k_out(const float* __restrict__ x,
                                             const float* __restrict__ w_out,
                                             const float* __restrict__ b_out,
                                             float* __restrict__ out) {
    __shared__ float qs[32 * 128];      // reused: first q rows, then oa rows
    __shared__ float ctxs[4096];
    __shared__ float Ws[16][132];

    const int tid  = threadIdx.x;
    const int row0 = blockIdx.x * 32;
    const int bi   = row0 >> 12;

    // load ctx for this batch
    #pragma unroll
    for (int i = 0; i < 16; ++i)
        ctxs[i * 256 + tid] = g_ctx[bi * 4096 + i * 256 + tid];

    // load q rows (qkv cols 0..127)
    {
        const int c4 = tid & 31, r0 = tid >> 5;
        #pragma unroll
        for (int p = 0; p < 4; ++p) {
            const int r = r0 + p * 8;
            float4 q = *(const float4*)(g_qkv + (size_t)(row0 + r) * QKVN + c4 * 4);
            *(float4*)&qs[r * 128 + c4 * 4] = q;
        }
    }
    __syncthreads();

    // oa[r][h*32+e] = sum_d q[r][h*32+d] * ctx[h][d][e]   (16 outputs/thread)
    float oa[16];
    {
        const int colb  = tid & 127;
        const int h     = colb >> 5;
        const int e     = colb & 31;
        const int rbase = tid >> 7;     // 0 or 1
        const float* ch = &ctxs[h * 1024];
        #pragma unroll
        for (int i = 0; i < 16; ++i) {
            const int r = rbase + i * 2;
            float a = 0.f;
            #pragma unroll
            for (int d = 0; d < 32; ++d)
                a = fmaf(qs[r * 128 + h * 32 + d], ch[d * 32 + e], a);
            oa[i] = a;
        }
    }
    __syncthreads();
    #pragma unroll
    for (int i = 0; i < 16; ++i) qs[i * 256 + tid] = oa[i];  // same o = r*128+col
    __syncthreads();

    // GEMM: out[32,1024] = oa[32,128] @ w_out[128,1024] (+ b_out + x)
    const int tx = tid & 31, ty = tid >> 5;  // cols tx*4, rows ty*4
    for (int nt = 0; nt < 8; ++nt) {
        float4 acc[4];
        #pragma unroll
        for (int i = 0; i < 4; ++i) acc[i] = make_float4(0.f, 0.f, 0.f, 0.f);

        for (int kt = 0; kt < 8; ++kt) {
            __syncthreads();
            {
                const int c4 = tid & 31, kr = tid >> 5;
                #pragma unroll
                for (int p = 0; p < 2; ++p)
                    *(float4*)&Ws[kr + p * 8][c4 * 4] =
                        *(const float4*)(w_out + (size_t)(kt * 16 + kr + p * 8) * DIM
                                         + nt * 128 + c4 * 4);
            }
            __syncthreads();
            #pragma unroll
            for (int kk = 0; kk < 16; ++kk) {
                const float4 bb = *(const float4*)&Ws[kk][tx * 4];
                #pragma unroll
                for (int i = 0; i < 4; ++i) {
                    const float a = qs[(ty * 4 + i) * 128 + kt * 16 + kk];
                    acc[i].x = fmaf(a, bb.x, acc[i].x);
                    acc[i].y = fmaf(a, bb.y, acc[i].y);
                    acc[i].z = fmaf(a, bb.z, acc[i].z);
                    acc[i].w = fmaf(a, bb.w, acc[i].w);
                }
            }
        }
        // epilogue: + b_out + x, write
        const int c = nt * 128 + tx * 4;
        const float4 bo = *(const float4*)(b_out + c);
        #pragma unroll
        for (int i = 0; i < 4; ++i) {
            const size_t r = (size_t)(row0 + ty * 4 + i);
            const float4 xb = *(const float4*)(x + r * DIM + c);
            float4 res;
            res.x = acc[i].x + bo.x + xb.x;
            res.y = acc[i].y + bo.y + xb.y;
            res.z = acc[i].z + bo.z + xb.z;
            res.w = acc[i].w + bo.w + xb.w;
            *(float4*)(out + r * DIM + c) = res;
        }
    }
}

// ---------------------------------------------------------------------------
extern "C" void kernel_launch(void* const* d_in, const int* in_sizes, int n_in,
                              void* d_out, int out_size) {
    const float* x     = (const float*)d_in[0];
    const float* gamma = (const float*)d_in[1];
    const float* beta  = (const float*)d_in[2];
    const float* wqkv  = (const float*)d_in[3];
    const float* wout  = (const float*)d_in[4];
    const float* bout  = (const float*)d_in[5];
    float* out = (float*)d_out;

    k_ln<<<ROWS, 256>>>(x, gamma, beta);
    k_gemm_qkv<<<dim3(3, ROWS / 128), 256>>>(wqkv);
    k_ctx_part<<<dim3(NCHUNK, HEADS, BATCH), 256>>>();
    k_ctx_reduce<<<32, 1024>>>();
    k_out<<<ROWS / 32, 256>>>(x, wout, bout, out);
}

// round 5
// speedup vs baseline: 3.6520x; 3.6520x over previous
#include <cuda_runtime.h>
#include <cuda_bf16.h>
#include <math.h>
#include <stdint.h>

// Problem constants
#define BATCH   8
#define SEQ     4096
#define DIM     1024
#define ROWS    (BATCH * SEQ)         // 32768
#define HEADS   4
#define DHEAD   32
#define HID     128
#define QKVN    384
#define NCHUNK  32
#define EPS     1e-5f
#define SCALE   0.17677669529663688f  // 32^-0.5

#define SWZ(o) ((o) ^ (((o) >> 3) & 0x70))

// ---------------------------------------------------------------------------
// Scratch (static device globals; allocation-free)
// ---------------------------------------------------------------------------
__device__ __align__(256) __nv_bfloat16 g_xn[(size_t)ROWS * DIM];       // 64 MB
__device__ __align__(256) float         g_qkv[(size_t)ROWS * QKVN];     // 48 MB
__device__ __align__(256) __nv_bfloat16 g_oa[(size_t)ROWS * HID];       // 8 MB
__device__ __align__(256) __nv_bfloat16 g_wqkvT[QKVN * DIM];            // [n][k]
__device__ __align__(256) __nv_bfloat16 g_woutT[DIM * HID];             // [n][k]
__device__ float g_pctx[NCHUNK * BATCH * HEADS * DHEAD * DHEAD];
__device__ float g_pS[NCHUNK * BATCH * HID];
__device__ float g_ctx[BATCH * HEADS * DHEAD * DHEAD];

// ---------------------------------------------------------------------------
// PTX helpers (sm_80-era, compile for plain compute_103)
// ---------------------------------------------------------------------------
__device__ __forceinline__ uint32_t smem_to_u32(const void* p) {
    uint32_t a;
    asm("{ .reg .u64 t; cvta.to.shared.u64 t, %1; cvt.u32.u64 %0, t; }"
        : "=r"(a) : "l"(p));
    return a;
}
__device__ __forceinline__ void cp_async16(uint32_t dst, const void* src) {
    asm volatile("cp.async.cg.shared.global [%0], [%1], 16;" :: "r"(dst), "l"(src));
}
__device__ __forceinline__ void cp_commit() {
    asm volatile("cp.async.commit_group;" ::: "memory");
}
__device__ __forceinline__ void cp_wait1() {
    asm volatile("cp.async.wait_group 1;" ::: "memory");
}
__device__ __forceinline__ void ldsm_x4(uint32_t& r0, uint32_t& r1,
                                        uint32_t& r2, uint32_t& r3, uint32_t a) {
    asm volatile("ldmatrix.sync.aligned.m8n8.x4.shared.b16 {%0,%1,%2,%3}, [%4];"
        : "=r"(r0), "=r"(r1), "=r"(r2), "=r"(r3) : "r"(a));
}
__device__ __forceinline__ void mma16816(float* d, const uint32_t* a, const uint32_t* b) {
    asm volatile("mma.sync.aligned.m16n8k16.row.col.f32.bf16.bf16.f32 "
        "{%0,%1,%2,%3}, {%4,%5,%6,%7}, {%8,%9}, {%0,%1,%2,%3};"
        : "+f"(d[0]), "+f"(d[1]), "+f"(d[2]), "+f"(d[3])
        : "r"(a[0]), "r"(a[1]), "r"(a[2]), "r"(a[3]), "r"(b[0]), "r"(b[1]));
}

// ---------------------------------------------------------------------------
// Generic HMMA GEMM body: C[M,N] = A[M,K](bf16,row) @ B[N,K](bf16,K-major)^T
// Block tile 128x128, BK=64, 256 threads (8 warps of 32x64), 2-stage cp.async.
// EPI: fused  + bias[col] + xres[row,col]  residual epilogue.
// Dynamic smem: 65536 B (2 stages x (16KB A + 16KB B)), SW128 swizzled.
//
// B fragment note: B is K-major ([n][k], k contiguous) == `col` layout for
// mma.row.col, so the correct load is ldmatrix WITHOUT .trans:
//   matrix0=(n0..7, k0..7) matrix1=(n0..7, k8..15)
//   matrix2=(n8..15,k0..7) matrix3=(n8..15,k8..15)
// giving fragments {r0,r1} for n-group 0 and {r2,r3} for n-group 1.
// ---------------------------------------------------------------------------
template<int LDA, int LDB, int LDC, int KITERS, bool EPI>
__device__ __forceinline__ void gemm_body(const __nv_bfloat16* __restrict__ A,
                                          const __nv_bfloat16* __restrict__ B,
                                          float* __restrict__ C,
                                          const float* __restrict__ bias,
                                          const float* __restrict__ xres,
                                          char* smem) {
    const uint32_t sb = smem_to_u32(smem);
    const int tid = threadIdx.x;
    const int lane = tid & 31, wid = tid >> 5;
    const int wm = wid & 3, wn = wid >> 2;
    const int rowg0 = blockIdx.y * 128;
    const int ncol0 = blockIdx.x * 128;

    const int lr = tid >> 3, lc = tid & 7;   // stage-fill indexing

    float acc[2][8][4];
    #pragma unroll
    for (int mt = 0; mt < 2; ++mt)
        #pragma unroll
        for (int nt = 0; nt < 8; ++nt)
            #pragma unroll
            for (int i = 0; i < 4; ++i) acc[mt][nt][i] = 0.f;

    auto load_stage = [&](int it, int stage) {
        const uint32_t Ao = (uint32_t)stage * 32768u;
        const uint32_t Bo = Ao + 16384u;
        const __nv_bfloat16* As = A + (size_t)rowg0 * LDA + it * 64;
        const __nv_bfloat16* Bs = B + (size_t)ncol0 * LDB + it * 64;
        #pragma unroll
        for (int p = 0; p < 4; ++p) {
            const int r = lr + p * 32;
            cp_async16(sb + Ao + SWZ((uint32_t)(r * 128 + lc * 16)),
                       As + (size_t)r * LDA + lc * 8);
        }
        #pragma unroll
        for (int p = 0; p < 4; ++p) {
            const int r = lr + p * 32;
            cp_async16(sb + Bo + SWZ((uint32_t)(r * 128 + lc * 16)),
                       Bs + (size_t)r * LDB + lc * 8);
        }
        cp_commit();
    };

    load_stage(0, 0);

    // precomputed ldmatrix lane offsets
    const int a_row = ((lane >> 3) & 1) * 8 + (lane & 7);
    const int a_kh  = (lane >> 4) * 8;
    const int b_nr  = (lane >> 4) * 8 + (lane & 7);
    const int b_kh  = ((lane >> 3) & 1) * 8;

    for (int it = 0; it < KITERS; ++it) {
        if (it + 1 < KITERS) load_stage(it + 1, (it + 1) & 1);
        else cp_commit();                      // keep group accounting uniform
        cp_wait1();
        __syncthreads();

        const uint32_t Ao = sb + (uint32_t)(it & 1) * 32768u;
        const uint32_t Bo = Ao + 16384u;

        #pragma unroll
        for (int ks = 0; ks < 4; ++ks) {
            uint32_t a[2][4];
            #pragma unroll
            for (int mt = 0; mt < 2; ++mt) {
                const int row = wm * 32 + mt * 16 + a_row;
                const int kc  = ks * 16 + a_kh;
                ldsm_x4(a[mt][0], a[mt][1], a[mt][2], a[mt][3],
                        Ao + SWZ((uint32_t)(row * 128 + kc * 2)));
            }
            uint32_t b[8][2];
            #pragma unroll
            for (int np = 0; np < 4; ++np) {
                const int nr = wn * 64 + np * 16 + b_nr;
                const int kc = ks * 16 + b_kh;
                ldsm_x4(b[np * 2][0], b[np * 2][1], b[np * 2 + 1][0], b[np * 2 + 1][1],
                        Bo + SWZ((uint32_t)(nr * 128 + kc * 2)));
            }
            #pragma unroll
            for (int mt = 0; mt < 2; ++mt)
                #pragma unroll
                for (int nt = 0; nt < 8; ++nt)
                    mma16816(acc[mt][nt], a[mt], b[nt]);
        }
        __syncthreads();
    }

    // Epilogue
    #pragma unroll
    for (int mt = 0; mt < 2; ++mt) {
        const int r0 = rowg0 + wm * 32 + mt * 16 + (lane >> 2);
        #pragma unroll
        for (int nt = 0; nt < 8; ++nt) {
            const int c = ncol0 + wn * 64 + nt * 8 + (lane & 3) * 2;
            float2 v0 = make_float2(acc[mt][nt][0], acc[mt][nt][1]);
            float2 v1 = make_float2(acc[mt][nt][2], acc[mt][nt][3]);
            if (EPI) {
                const float2 bo = *(const float2*)(bias + c);
                const float2 x0 = *(const float2*)(xres + (size_t)r0 * LDC + c);
                const float2 x1 = *(const float2*)(xres + (size_t)(r0 + 8) * LDC + c);
                v0.x += bo.x + x0.x; v0.y += bo.y + x0.y;
                v1.x += bo.x + x1.x; v1.y += bo.y + x1.y;
            }
            *(float2*)(C + (size_t)r0 * LDC + c) = v0;
            *(float2*)(C + (size_t)(r0 + 8) * LDC + c) = v1;
        }
    }
}

// grid (3, 256): qkv = xn @ wqkvT^T
__global__ __launch_bounds__(256, 1) void k_qkv_mma() {
    extern __shared__ __align__(1024) char smem[];
    gemm_body<DIM, DIM, QKVN, 16, false>(g_xn, g_wqkvT, g_qkv, nullptr, nullptr, smem);
}
// grid (8, 256): out = oa @ woutT^T + b_out + x
__global__ __launch_bounds__(256, 1) void k_out_mma(const float* __restrict__ x,
                                                    const float* __restrict__ b_out,
                                                    float* __restrict__ out) {
    extern __shared__ __align__(1024) char smem[];
    gemm_body<HID, HID, DIM, 2, true>(g_oa, g_woutT, out, b_out, x, smem);
}

// ---------------------------------------------------------------------------
// K0: weight prep (transpose + bf16)
// ---------------------------------------------------------------------------
__global__ __launch_bounds__(256) void k_prep(const float* __restrict__ wqkv,
                                              const float* __restrict__ wout) {
    const int idx = blockIdx.x * 256 + threadIdx.x;
    if (idx < QKVN * DIM) {
        const int n = idx >> 10, k = idx & 1023;
        g_wqkvT[idx] = __float2bfloat16(wqkv[k * QKVN + n]);
    }
    if (idx < DIM * HID) {
        const int n = idx >> 7, k = idx & 127;
        g_woutT[idx] = __float2bfloat16(wout[k * DIM + n]);
    }
}

// ---------------------------------------------------------------------------
// K1: LayerNorm -> bf16
// ---------------------------------------------------------------------------
__global__ __launch_bounds__(256) void k_ln(const float* __restrict__ x,
                                            const float* __restrict__ gamma,
                                            const float* __restrict__ beta) {
    const int row = blockIdx.x;
    const int tid = threadIdx.x;
    const float4 f = ((const float4*)(x + (size_t)row * DIM))[tid];

    float s  = f.x + f.y + f.z + f.w;
    float s2 = fmaf(f.x, f.x, fmaf(f.y, f.y, fmaf(f.z, f.z, f.w * f.w)));
    #pragma unroll
    for (int off = 16; off > 0; off >>= 1) {
        s  += __shfl_xor_sync(0xffffffffu, s,  off);
        s2 += __shfl_xor_sync(0xffffffffu, s2, off);
    }
    __shared__ float red[16];
    const int wid = tid >> 5, lane = tid & 31;
    if (lane == 0) { red[wid] = s; red[8 + wid] = s2; }
    __syncthreads();
    float ts = 0.f, ts2 = 0.f;
    #pragma unroll
    for (int w = 0; w < 8; ++w) { ts += red[w]; ts2 += red[8 + w]; }

    const float mean = ts * (1.0f / DIM);
    const float var  = ts2 * (1.0f / DIM) - mean * mean;
    const float rstd = rsqrtf(var + EPS);

    const float4 g  = ((const float4*)gamma)[tid];
    const float4 be = ((const float4*)beta)[tid];
    __nv_bfloat162 p0, p1;
    p0.x = __float2bfloat16((f.x - mean) * rstd * g.x + be.x);
    p0.y = __float2bfloat16((f.y - mean) * rstd * g.y + be.y);
    p1.x = __float2bfloat16((f.z - mean) * rstd * g.z + be.z);
    p1.y = __float2bfloat16((f.w - mean) * rstd * g.w + be.w);
    __nv_bfloat162* o = (__nv_bfloat162*)(g_xn + (size_t)row * DIM);
    o[tid * 2 + 0] = p0;
    o[tid * 2 + 1] = p1;
}

// ---------------------------------------------------------------------------
// K3: per-chunk partials of exp(k)*v and column-sums of exp(k)
// ---------------------------------------------------------------------------
__global__ __launch_bounds__(256) void k_ctx_part() {
    const int chunk = blockIdx.x, h = blockIdx.y, b = blockIdx.z;
    const int tid = threadIdx.x;

    __shared__ float ks[128][32];
    __shared__ float vs[128][32];

    const int f4 = tid & 7;
    const int r0 = tid >> 3;
    const size_t base = (size_t)(b * SEQ + chunk * 128) * QKVN;
    #pragma unroll
    for (int p = 0; p < 4; ++p) {
        const int r = r0 + p * 32;
        const size_t rb = base + (size_t)r * QKVN;
        float4 kv = *(const float4*)(g_qkv + rb + HID + h * DHEAD + f4 * 4);
        ks[r][f4 * 4 + 0] = expf(kv.x);
        ks[r][f4 * 4 + 1] = expf(kv.y);
        ks[r][f4 * 4 + 2] = expf(kv.z);
        ks[r][f4 * 4 + 3] = expf(kv.w);
        *(float4*)&vs[r][f4 * 4] =
            *(const float4*)(g_qkv + rb + 2 * HID + h * DHEAD + f4 * 4);
    }
    __syncthreads();

    if (tid < 32) {
        float s = 0.f;
        #pragma unroll
        for (int r = 0; r < 128; ++r) s += ks[r][tid];
        g_pS[chunk * (BATCH * HID) + b * HID + h * DHEAD + tid] = s;
    }

    const int e = tid & 31;
    const int d0 = tid >> 5;
    float acc[4] = {0.f, 0.f, 0.f, 0.f};
    for (int r = 0; r < 128; ++r) {
        const float ve = vs[r][e];
        #pragma unroll
        for (int i = 0; i < 4; ++i)
            acc[i] = fmaf(ks[r][d0 + i * 8], ve, acc[i]);
    }
    const size_t ob = (size_t)chunk * 32768 + (size_t)b * 4096 + (size_t)h * 1024;
    #pragma unroll
    for (int i = 0; i < 4; ++i)
        g_pctx[ob + (size_t)(d0 + i * 8) * 32 + e] = acc[i];
}

// ---------------------------------------------------------------------------
// K4: reduce partials, fold softmax normalization + q-scale into ctx
// ---------------------------------------------------------------------------
__global__ __launch_bounds__(1024) void k_ctx_reduce() {
    const int o  = blockIdx.x * 1024 + threadIdx.x;
    const int bi = o >> 12;
    const int hd = (o >> 5) & 127;
    float s = 0.f, S = 0.f;
    #pragma unroll
    for (int c = 0; c < NCHUNK; ++c) {
        s += g_pctx[(size_t)c * 32768 + o];
        S += g_pS[c * (BATCH * HID) + bi * HID + hd];
    }
    g_ctx[o] = s * SCALE / S;
}

// ---------------------------------------------------------------------------
// K5: oa = q @ ctx  -> bf16   (grid 256, 256 threads, dyn smem 81920)
// ---------------------------------------------------------------------------
__global__ __launch_bounds__(256, 1) void k_oa() {
    extern __shared__ char smem[];
    float* ctxs = (float*)smem;              // 16 KB
    float* qs   = (float*)(smem + 16384);    // 64 KB: [128][128]

    const int tid = threadIdx.x;
    const size_t rowg0 = (size_t)blockIdx.x * 128;
    const int bi = (int)(rowg0 >> 12);

    #pragma unroll
    for (int i = 0; i < 16; ++i)
        ctxs[i * 256 + tid] = g_ctx[bi * 4096 + i * 256 + tid];
    #pragma unroll
    for (int p = 0; p < 16; ++p) {
        const int idx = tid + p * 256;
        const int r = idx >> 5, c = idx & 31;
        ((float4*)qs)[r * 32 + c] =
            *(const float4*)(g_qkv + (rowg0 + r) * QKVN + c * 4);
    }
    __syncthreads();

    const int col = tid & 127, rh = tid >> 7;
    const int h = col >> 5, e = col & 31;
    float cv[32];
    #pragma unroll
    for (int d = 0; d < 32; ++d) cv[d] = ctxs[h * 1024 + d * 32 + e];

    for (int rr = 0; rr < 64; ++rr) {
        const int r = rh * 64 + rr;
        const float* qrow = qs + r * 128 + h * 32;
        float a = 0.f;
        #pragma unroll
        for (int d = 0; d < 32; ++d) a = fmaf(qrow[d], cv[d], a);
        g_oa[(rowg0 + r) * HID + col] = __float2bfloat16(a);
    }
}

// ---------------------------------------------------------------------------
extern "C" void kernel_launch(void* const* d_in, const int* in_sizes, int n_in,
                              void* d_out, int out_size) {
    const float* x     = (const float*)d_in[0];
    const float* gamma = (const float*)d_in[1];
    const float* beta  = (const float*)d_in[2];
    const float* wqkv  = (const float*)d_in[3];
    const float* wout  = (const float*)d_in[4];
    const float* bout  = (const float*)d_in[5];
    float* out = (float*)d_out;

    cudaFuncSetAttribute(k_qkv_mma, cudaFuncAttributeMaxDynamicSharedMemorySize, 65536);
    cudaFuncSetAttribute(k_out_mma, cudaFuncAttributeMaxDynamicSharedMemorySize, 65536);
    cudaFuncSetAttribute(k_oa,      cudaFuncAttributeMaxDynamicSharedMemorySize, 81920);

    k_prep<<<1536, 256>>>(wqkv, wout);
    k_ln<<<ROWS, 256>>>(x, gamma, beta);
    k_qkv_mma<<<dim3(3, 256), 256, 65536>>>();
    k_ctx_part<<<dim3(NCHUNK, HEADS, BATCH), 256>>>();
    k_ctx_reduce<<<32, 1024>>>();
    k_oa<<<256, 256, 81920>>>();
    k_out_mma<<<dim3(8, 256), 256, 65536>>>(x, bout, out);
}

// round 6
// speedup vs baseline: 4.4766x; 1.2258x over previous
#include <cuda_runtime.h>
#include <cuda_bf16.h>
#include <math.h>
#include <stdint.h>

// Problem constants
#define BATCH   8
#define SEQ     4096
#define DIM     1024
#define ROWS    (BATCH * SEQ)         // 32768
#define HEADS   4
#define DHEAD   32
#define HID     128
#define QKVN    384
#define NCHUNK  32
#define EPS     1e-5f
#define SCALE   0.17677669529663688f  // 32^-0.5

#define SWZ(o) ((o) ^ (((o) >> 3) & 0x70))

// ---------------------------------------------------------------------------
// Scratch (static device globals; allocation-free)
// ---------------------------------------------------------------------------
__device__ __align__(256) __nv_bfloat16 g_xn[(size_t)ROWS * DIM];       // 64 MB
__device__ __align__(256) float         g_qkv[(size_t)ROWS * QKVN];     // 48 MB
__device__ __align__(256) __nv_bfloat16 g_oa[(size_t)ROWS * HID];       // 8 MB
__device__ __align__(256) __nv_bfloat16 g_wqkvT[QKVN * DIM];            // [n][k]
__device__ __align__(256) __nv_bfloat16 g_woutT[DIM * HID];             // [n][k]
__device__ float g_pctx[NCHUNK * BATCH * HEADS * DHEAD * DHEAD];
__device__ float g_pS[NCHUNK * BATCH * HID];
__device__ float g_ctx[BATCH * HEADS * DHEAD * DHEAD];

// ---------------------------------------------------------------------------
// PTX helpers (sm_80-era, compile for plain compute_103)
// ---------------------------------------------------------------------------
__device__ __forceinline__ uint32_t smem_to_u32(const void* p) {
    uint32_t a;
    asm("{ .reg .u64 t; cvta.to.shared.u64 t, %1; cvt.u32.u64 %0, t; }"
        : "=r"(a) : "l"(p));
    return a;
}
__device__ __forceinline__ void cp_async16(uint32_t dst, const void* src) {
    asm volatile("cp.async.cg.shared.global [%0], [%1], 16;" :: "r"(dst), "l"(src));
}
__device__ __forceinline__ void cp_commit() {
    asm volatile("cp.async.commit_group;" ::: "memory");
}
__device__ __forceinline__ void cp_wait1() {
    asm volatile("cp.async.wait_group 1;" ::: "memory");
}
__device__ __forceinline__ void ldsm_x4(uint32_t& r0, uint32_t& r1,
                                        uint32_t& r2, uint32_t& r3, uint32_t a) {
    asm volatile("ldmatrix.sync.aligned.m8n8.x4.shared.b16 {%0,%1,%2,%3}, [%4];"
        : "=r"(r0), "=r"(r1), "=r"(r2), "=r"(r3) : "r"(a));
}
__device__ __forceinline__ void mma16816(float* d, const uint32_t* a, const uint32_t* b) {
    asm volatile("mma.sync.aligned.m16n8k16.row.col.f32.bf16.bf16.f32 "
        "{%0,%1,%2,%3}, {%4,%5,%6,%7}, {%8,%9}, {%0,%1,%2,%3};"
        : "+f"(d[0]), "+f"(d[1]), "+f"(d[2]), "+f"(d[3])
        : "r"(a[0]), "r"(a[1]), "r"(a[2]), "r"(a[3]), "r"(b[0]), "r"(b[1]));
}

// ---------------------------------------------------------------------------
// Generic HMMA GEMM body: C[M,N] = A[M,K](bf16,row) @ B[N,K](bf16,K-major)^T
// Block tile 128x128, BK=64, 256 threads (8 warps of 32x64), 2-stage cp.async.
// EPI: fused  + bias[col] + xres[row,col]  residual epilogue.
// Dynamic smem: 65536 B (2 stages x (16KB A + 16KB B)), SW128 swizzled.
// B is K-major == `col` layout for mma.row.col -> plain ldmatrix (no .trans).
// ---------------------------------------------------------------------------
template<int LDA, int LDB, int LDC, int KITERS, bool EPI>
__device__ __forceinline__ void gemm_body(const __nv_bfloat16* __restrict__ A,
                                          const __nv_bfloat16* __restrict__ B,
                                          float* __restrict__ C,
                                          const float* __restrict__ bias,
                                          const float* __restrict__ xres,
                                          char* smem) {
    const uint32_t sb = smem_to_u32(smem);
    const int tid = threadIdx.x;
    const int lane = tid & 31, wid = tid >> 5;
    const int wm = wid & 3, wn = wid >> 2;
    const int rowg0 = blockIdx.y * 128;
    const int ncol0 = blockIdx.x * 128;

    const int lr = tid >> 3, lc = tid & 7;   // stage-fill indexing

    float acc[2][8][4];
    #pragma unroll
    for (int mt = 0; mt < 2; ++mt)
        #pragma unroll
        for (int nt = 0; nt < 8; ++nt)
            #pragma unroll
            for (int i = 0; i < 4; ++i) acc[mt][nt][i] = 0.f;

    auto load_stage = [&](int it, int stage) {
        const uint32_t Ao = (uint32_t)stage * 32768u;
        const uint32_t Bo = Ao + 16384u;
        const __nv_bfloat16* As = A + (size_t)rowg0 * LDA + it * 64;
        const __nv_bfloat16* Bs = B + (size_t)ncol0 * LDB + it * 64;
        #pragma unroll
        for (int p = 0; p < 4; ++p) {
            const int r = lr + p * 32;
            cp_async16(sb + Ao + SWZ((uint32_t)(r * 128 + lc * 16)),
                       As + (size_t)r * LDA + lc * 8);
        }
        #pragma unroll
        for (int p = 0; p < 4; ++p) {
            const int r = lr + p * 32;
            cp_async16(sb + Bo + SWZ((uint32_t)(r * 128 + lc * 16)),
                       Bs + (size_t)r * LDB + lc * 8);
        }
        cp_commit();
    };

    load_stage(0, 0);

    // precomputed ldmatrix lane offsets
    const int a_row = ((lane >> 3) & 1) * 8 + (lane & 7);
    const int a_kh  = (lane >> 4) * 8;
    const int b_nr  = (lane >> 4) * 8 + (lane & 7);
    const int b_kh  = ((lane >> 3) & 1) * 8;

    for (int it = 0; it < KITERS; ++it) {
        if (it + 1 < KITERS) load_stage(it + 1, (it + 1) & 1);
        else cp_commit();                      // keep group accounting uniform
        cp_wait1();
        __syncthreads();

        const uint32_t Ao = sb + (uint32_t)(it & 1) * 32768u;
        const uint32_t Bo = Ao + 16384u;

        #pragma unroll
        for (int ks = 0; ks < 4; ++ks) {
            uint32_t a[2][4];
            #pragma unroll
            for (int mt = 0; mt < 2; ++mt) {
                const int row = wm * 32 + mt * 16 + a_row;
                const int kc  = ks * 16 + a_kh;
                ldsm_x4(a[mt][0], a[mt][1], a[mt][2], a[mt][3],
                        Ao + SWZ((uint32_t)(row * 128 + kc * 2)));
            }
            uint32_t b[8][2];
            #pragma unroll
            for (int np = 0; np < 4; ++np) {
                const int nr = wn * 64 + np * 16 + b_nr;
                const int kc = ks * 16 + b_kh;
                ldsm_x4(b[np * 2][0], b[np * 2][1], b[np * 2 + 1][0], b[np * 2 + 1][1],
                        Bo + SWZ((uint32_t)(nr * 128 + kc * 2)));
            }
            #pragma unroll
            for (int mt = 0; mt < 2; ++mt)
                #pragma unroll
                for (int nt = 0; nt < 8; ++nt)
                    mma16816(acc[mt][nt], a[mt], b[nt]);
        }
        __syncthreads();
    }

    // Epilogue
    #pragma unroll
    for (int mt = 0; mt < 2; ++mt) {
        const int r0 = rowg0 + wm * 32 + mt * 16 + (lane >> 2);
        #pragma unroll
        for (int nt = 0; nt < 8; ++nt) {
            const int c = ncol0 + wn * 64 + nt * 8 + (lane & 3) * 2;
            float2 v0 = make_float2(acc[mt][nt][0], acc[mt][nt][1]);
            float2 v1 = make_float2(acc[mt][nt][2], acc[mt][nt][3]);
            if (EPI) {
                const float2 bo = *(const float2*)(bias + c);
                const float2 x0 = *(const float2*)(xres + (size_t)r0 * LDC + c);
                const float2 x1 = *(const float2*)(xres + (size_t)(r0 + 8) * LDC + c);
                v0.x += bo.x + x0.x; v0.y += bo.y + x0.y;
                v1.x += bo.x + x1.x; v1.y += bo.y + x1.y;
            }
            *(float2*)(C + (size_t)r0 * LDC + c) = v0;
            *(float2*)(C + (size_t)(r0 + 8) * LDC + c) = v1;
        }
    }
}

// grid (3, 256): qkv = xn @ wqkvT^T     (2 blocks/SM to hide sync/ldsm latency)
__global__ __launch_bounds__(256, 2) void k_qkv_mma() {
    extern __shared__ __align__(1024) char smem[];
    gemm_body<DIM, DIM, QKVN, 16, false>(g_xn, g_wqkvT, g_qkv, nullptr, nullptr, smem);
}
// grid (8, 256): out = oa @ woutT^T + b_out + x
__global__ __launch_bounds__(256, 2) void k_out_mma(const float* __restrict__ x,
                                                    const float* __restrict__ b_out,
                                                    float* __restrict__ out) {
    extern __shared__ __align__(1024) char smem[];
    gemm_body<HID, HID, DIM, 2, true>(g_oa, g_woutT, out, b_out, x, smem);
}

// ---------------------------------------------------------------------------
// K0: weight prep (transpose + bf16)
// ---------------------------------------------------------------------------
__global__ __launch_bounds__(256) void k_prep(const float* __restrict__ wqkv,
                                              const float* __restrict__ wout) {
    const int idx = blockIdx.x * 256 + threadIdx.x;
    if (idx < QKVN * DIM) {
        const int n = idx >> 10, k = idx & 1023;
        g_wqkvT[idx] = __float2bfloat16(wqkv[k * QKVN + n]);
    }
    if (idx < DIM * HID) {
        const int n = idx >> 7, k = idx & 127;
        g_woutT[idx] = __float2bfloat16(wout[k * DIM + n]);
    }
}

// ---------------------------------------------------------------------------
// K1: LayerNorm -> bf16
// ---------------------------------------------------------------------------
__global__ __launch_bounds__(256) void k_ln(const float* __restrict__ x,
                                            const float* __restrict__ gamma,
                                            const float* __restrict__ beta) {
    const int row = blockIdx.x;
    const int tid = threadIdx.x;
    const float4 f = ((const float4*)(x + (size_t)row * DIM))[tid];

    float s  = f.x + f.y + f.z + f.w;
    float s2 = fmaf(f.x, f.x, fmaf(f.y, f.y, fmaf(f.z, f.z, f.w * f.w)));
    #pragma unroll
    for (int off = 16; off > 0; off >>= 1) {
        s  += __shfl_xor_sync(0xffffffffu, s,  off);
        s2 += __shfl_xor_sync(0xffffffffu, s2, off);
    }
    __shared__ float red[16];
    const int wid = tid >> 5, lane = tid & 31;
    if (lane == 0) { red[wid] = s; red[8 + wid] = s2; }
    __syncthreads();
    float ts = 0.f, ts2 = 0.f;
    #pragma unroll
    for (int w = 0; w < 8; ++w) { ts += red[w]; ts2 += red[8 + w]; }

    const float mean = ts * (1.0f / DIM);
    const float var  = ts2 * (1.0f / DIM) - mean * mean;
    const float rstd = rsqrtf(var + EPS);

    const float4 g  = ((const float4*)gamma)[tid];
    const float4 be = ((const float4*)beta)[tid];
    __nv_bfloat162 p0, p1;
    p0.x = __float2bfloat16((f.x - mean) * rstd * g.x + be.x);
    p0.y = __float2bfloat16((f.y - mean) * rstd * g.y + be.y);
    p1.x = __float2bfloat16((f.z - mean) * rstd * g.z + be.z);
    p1.y = __float2bfloat16((f.w - mean) * rstd * g.w + be.w);
    __nv_bfloat162* o = (__nv_bfloat162*)(g_xn + (size_t)row * DIM);
    o[tid * 2 + 0] = p0;
    o[tid * 2 + 1] = p1;
}

// ---------------------------------------------------------------------------
// K3: per-chunk partials of exp(k)*v and column-sums of exp(k)
// Thread map: e = tid&31, d4 = tid>>5 -> d in [d4*4, d4*4+4): one broadcast
// LDS.128 (ks) + one stride-1 LDS.32 (vs) per 4 FFMA.
// ---------------------------------------------------------------------------
__global__ __launch_bounds__(256) void k_ctx_part() {
    const int chunk = blockIdx.x, h = blockIdx.y, b = blockIdx.z;
    const int tid = threadIdx.x;

    __shared__ __align__(16) float ks[128][32];
    __shared__ __align__(16) float vs[128][32];

    const int f4 = tid & 7;
    const int r0 = tid >> 3;
    const size_t base = (size_t)(b * SEQ + chunk * 128) * QKVN;
    #pragma unroll
    for (int p = 0; p < 4; ++p) {
        const int r = r0 + p * 32;
        const size_t rb = base + (size_t)r * QKVN;
        float4 kv = *(const float4*)(g_qkv + rb + HID + h * DHEAD + f4 * 4);
        ks[r][f4 * 4 + 0] = __expf(kv.x);
        ks[r][f4 * 4 + 1] = __expf(kv.y);
        ks[r][f4 * 4 + 2] = __expf(kv.z);
        ks[r][f4 * 4 + 3] = __expf(kv.w);
        *(float4*)&vs[r][f4 * 4] =
            *(const float4*)(g_qkv + rb + 2 * HID + h * DHEAD + f4 * 4);
    }
    __syncthreads();

    if (tid < 32) {
        float s = 0.f;
        #pragma unroll
        for (int r = 0; r < 128; ++r) s += ks[r][tid];
        g_pS[chunk * (BATCH * HID) + b * HID + h * DHEAD + tid] = s;
    }

    const int e  = tid & 31;
    const int d4 = tid >> 5;      // d base = d4*4, contiguous
    float acc[4] = {0.f, 0.f, 0.f, 0.f};
    #pragma unroll 4
    for (int r = 0; r < 128; ++r) {
        const float4 kk = *(const float4*)&ks[r][d4 * 4];   // warp-broadcast
        const float ve = vs[r][e];                          // stride-1
        acc[0] = fmaf(kk.x, ve, acc[0]);
        acc[1] = fmaf(kk.y, ve, acc[1]);
        acc[2] = fmaf(kk.z, ve, acc[2]);
        acc[3] = fmaf(kk.w, ve, acc[3]);
    }
    const size_t ob = (size_t)chunk * 32768 + (size_t)b * 4096 + (size_t)h * 1024;
    #pragma unroll
    for (int i = 0; i < 4; ++i)
        g_pctx[ob + (size_t)(d4 * 4 + i) * 32 + e] = acc[i];
}

// ---------------------------------------------------------------------------
// K4: reduce partials, fold softmax normalization + q-scale into ctx
// ---------------------------------------------------------------------------
__global__ __launch_bounds__(1024) void k_ctx_reduce() {
    const int o  = blockIdx.x * 1024 + threadIdx.x;
    const int bi = o >> 12;
    const int hd = (o >> 5) & 127;
    float s = 0.f, S = 0.f;
    #pragma unroll
    for (int c = 0; c < NCHUNK; ++c) {
        s += g_pctx[(size_t)c * 32768 + o];
        S += g_pS[c * (BATCH * HID) + bi * HID + hd];
    }
    g_ctx[o] = s * SCALE / S;
}

// ---------------------------------------------------------------------------
// K5: oa = q @ ctx  -> bf16   (grid 256, 256 threads, dyn smem 81920)
// ---------------------------------------------------------------------------
__global__ __launch_bounds__(256, 1) void k_oa() {
    extern __shared__ char smem[];
    float* ctxs = (float*)smem;              // 16 KB
    float* qs   = (float*)(smem + 16384);    // 64 KB: [128][128]

    const int tid = threadIdx.x;
    const size_t rowg0 = (size_t)blockIdx.x * 128;
    const int bi = (int)(rowg0 >> 12);

    #pragma unroll
    for (int i = 0; i < 16; ++i)
        ctxs[i * 256 + tid] = g_ctx[bi * 4096 + i * 256 + tid];
    #pragma unroll
    for (int p = 0; p < 16; ++p) {
        const int idx = tid + p * 256;
        const int r = idx >> 5, c = idx & 31;
        ((float4*)qs)[r * 32 + c] =
            *(const float4*)(g_qkv + (rowg0 + r) * QKVN + c * 4);
    }
    __syncthreads();

    const int col = tid & 127, rh = tid >> 7;
    const int h = col >> 5, e = col & 31;
    float cv[32];
    #pragma unroll
    for (int d = 0; d < 32; ++d) cv[d] = ctxs[h * 1024 + d * 32 + e];

    for (int rr = 0; rr < 64; ++rr) {
        const int r = rh * 64 + rr;
        const float* qrow = qs + r * 128 + h * 32;
        float a = 0.f;
        #pragma unroll
        for (int d = 0; d < 32; ++d) a = fmaf(qrow[d], cv[d], a);
        g_oa[(rowg0 + r) * HID + col] = __float2bfloat16(a);
    }
}

// ---------------------------------------------------------------------------
extern "C" void kernel_launch(void* const* d_in, const int* in_sizes, int n_in,
                              void* d_out, int out_size) {
    const float* x     = (const float*)d_in[0];
    const float* gamma = (const float*)d_in[1];
    const float* beta  = (const float*)d_in[2];
    const float* wqkv  = (const float*)d_in[3];
    const float* wout  = (const float*)d_in[4];
    const float* bout  = (const float*)d_in[5];
    float* out = (float*)d_out;

    cudaFuncSetAttribute(k_qkv_mma, cudaFuncAttributeMaxDynamicSharedMemorySize, 65536);
    cudaFuncSetAttribute(k_out_mma, cudaFuncAttributeMaxDynamicSharedMemorySize, 65536);
    cudaFuncSetAttribute(k_oa,      cudaFuncAttributeMaxDynamicSharedMemorySize, 81920);

    k_prep<<<1536, 256>>>(wqkv, wout);
    k_ln<<<ROWS, 256>>>(x, gamma, beta);
    k_qkv_mma<<<dim3(3, 256), 256, 65536>>>();
    k_ctx_part<<<dim3(NCHUNK, HEADS, BATCH), 256>>>();
    k_ctx_reduce<<<32, 1024>>>();
    k_oa<<<256, 256, 81920>>>();
    k_out_mma<<<dim3(8, 256), 256, 65536>>>(x, bout, out);
}